// round 7
// baseline (speedup 1.0000x reference)
#include <cuda_runtime.h>
#include <cuda_bf16.h>
#include <cstddef>
#include <cstdint>

#define NU_MAX 100000
#define NI_MAX 100000
#define E_MAX  1000000
#define DIMN   128

// ---------------- scratch (static __device__, no allocation) ----------------
__device__ int   g_cnt[3][NU_MAX + 1];
__device__ int   g_off[3][NU_MAX + 1];
__device__ int   g_cur[3][NU_MAX];
__device__ int   g_adj[3][E_MAX];
__device__ float g_meanB[(size_t)NI_MAX * DIMN];
__device__ float g_meanR[(size_t)NU_MAX * DIMN];
__device__ float g_meanT[(size_t)NI_MAX * DIMN];

// split + transposed weights: [panel][half hi/lo][n*128+k] bf16
__device__ __align__(16) __nv_bfloat16 g_Wsp[5][2][DIMN * DIMN];
__device__ __align__(16) float g_biasU[DIMN];
__device__ __align__(16) float g_biasI[DIMN];

// ---------------- init: zero counters + weight prep (merged) ----------------
__global__ void k_init(const float* __restrict__ WlR, const float* __restrict__ WrR,
                       const float* __restrict__ WlB, const float* __restrict__ WlT,
                       const float* __restrict__ WrB, const float* __restrict__ WrT,
                       const float* __restrict__ bR, const float* __restrict__ bB,
                       const float* __restrict__ bT) {
    int i = blockIdx.x * blockDim.x + threadIdx.x;
    const int total = 3 * (NU_MAX + 1);
    if (i < total) ((int*)g_cnt)[i] = 0;
    if (i < 5 * 16384) {
        int panel = i >> 14;
        int e = i & 16383;
        int k = e >> 7;
        int n = e & 127;
        float v;
        switch (panel) {
            case 0:  v = WlR[k * 128 + n]; break;
            case 1:  v = WrR[k * 128 + n]; break;
            case 2:  v = 0.5f * WlB[k * 128 + n]; break;
            case 3:  v = 0.5f * WlT[k * 128 + n]; break;
            default: v = 0.5f * (WrB[k * 128 + n] + WrT[k * 128 + n]);
        }
        __nv_bfloat16 h = __float2bfloat16_rn(v);
        __nv_bfloat16 l = __float2bfloat16_rn(v - __bfloat162float(h));
        g_Wsp[panel][0][n * 128 + k] = h;
        g_Wsp[panel][1][n * 128 + k] = l;
    }
    if (i < DIMN) {
        g_biasU[i] = bR[i];
        g_biasI[i] = 0.5f * (bB[i] + bT[i]);
    }
}

// ---------------- CSR build ----------------
__global__ void k_hist3(const int* __restrict__ db, const int* __restrict__ dr,
                        const int* __restrict__ dt, int EB, int ER, int ET) {
    int t = blockIdx.x * blockDim.x + threadIdx.x;
    #pragma unroll
    for (int j = 0; j < 2; j++) {
        int e = t * 2 + j;
        if (e < EB) atomicAdd(&g_cnt[0][__ldcs(&db[e])], 1);
        else if (e < EB + ER) atomicAdd(&g_cnt[1][__ldcs(&dr[e - EB])], 1);
        else if (e < EB + ER + ET) atomicAdd(&g_cnt[2][__ldcs(&dt[e - EB - ER])], 1);
    }
}

// warp-shuffle based exclusive scan; 3 blocks (one per relation), 1024 threads
__global__ void k_scan(int n0, int n1, int n2) {
    int rel = blockIdx.x;
    int n = (rel == 0) ? n0 : (rel == 1) ? n1 : n2;
    int lane = threadIdx.x & 31, wid = threadIdx.x >> 5;
    __shared__ int wsum[32];
    __shared__ int carry;
    if (threadIdx.x == 0) carry = 0;
    __syncthreads();
    for (int base = 0; base < n; base += 1024) {
        int i = base + threadIdx.x;
        int v = (i < n) ? g_cnt[rel][i] : 0;
        int s = v;
        #pragma unroll
        for (int d = 1; d < 32; d <<= 1) {
            int t = __shfl_up_sync(0xFFFFFFFFu, s, d);
            if (lane >= d) s += t;
        }
        if (lane == 31) wsum[wid] = s;
        __syncthreads();
        if (wid == 0) {
            int w = wsum[lane];
            #pragma unroll
            for (int d = 1; d < 32; d <<= 1) {
                int t = __shfl_up_sync(0xFFFFFFFFu, w, d);
                if (lane >= d) w += t;
            }
            wsum[lane] = w;
        }
        __syncthreads();
        int woff = (wid > 0) ? wsum[wid - 1] : 0;
        int c = carry;
        int excl = c + woff + s - v;
        if (i < n) { g_off[rel][i] = excl; g_cur[rel][i] = excl; }
        int tot = wsum[31];
        __syncthreads();
        if (threadIdx.x == 0) carry = c + tot;
        __syncthreads();
    }
    if (threadIdx.x == 0) g_off[rel][n] = carry;
}

__global__ void k_fill3(const int* __restrict__ eb, const int* __restrict__ er,
                        const int* __restrict__ et, int EB, int ER, int ET) {
    int t = blockIdx.x * blockDim.x + threadIdx.x;
    #pragma unroll
    for (int j = 0; j < 2; j++) {
        int e = t * 2 + j;
        int rel, idx;
        const int* ei;
        int E;
        if (e < EB) { rel = 0; idx = e; ei = eb; E = EB; }
        else if (e < EB + ER) { rel = 1; idx = e - EB; ei = er; E = ER; }
        else if (e < EB + ER + ET) { rel = 2; idx = e - EB - ER; ei = et; E = ET; }
        else continue;
        int d = __ldcs(&ei[E + idx]);
        int s = __ldcs(&ei[idx]);
        int p = atomicAdd(&g_cur[rel][d], 1);
        g_adj[rel][p] = s;
    }
}

// ---------------- mean aggregation: one warp per dst node, unroll-4 ----------------
__global__ void k_agg3(const float* __restrict__ xu, const float* __restrict__ xi,
                       const float* __restrict__ xt, int NU, int NI) {
    int w = (blockIdx.x * blockDim.x + threadIdx.x) >> 5;
    int lane = threadIdx.x & 31;
    int rel, node;
    const float* xs;
    float* mean;
    if (w < NI) { rel = 0; node = w; xs = xu; mean = g_meanB; }
    else if (w < NI + NU) { rel = 1; node = w - NI; xs = xi; mean = g_meanR; }
    else if (w < NI + NU + NI) { rel = 2; node = w - NI - NU; xs = xt; mean = g_meanT; }
    else return;

    const int* __restrict__ adj = g_adj[rel];
    int s0 = g_off[rel][node], s1 = g_off[rel][node + 1];
    float4 a0 = make_float4(0.f, 0.f, 0.f, 0.f);
    float4 a1 = make_float4(0.f, 0.f, 0.f, 0.f);
    float4 a2 = make_float4(0.f, 0.f, 0.f, 0.f);
    float4 a3 = make_float4(0.f, 0.f, 0.f, 0.f);
    int e = s0;
    for (; e + 3 < s1; e += 4) {
        int i0 = __ldcs(&adj[e]);
        int i1 = __ldcs(&adj[e + 1]);
        int i2 = __ldcs(&adj[e + 2]);
        int i3 = __ldcs(&adj[e + 3]);
        float4 v0 = __ldcg((const float4*)(xs + (size_t)i0 * DIMN + lane * 4));
        float4 v1 = __ldcg((const float4*)(xs + (size_t)i1 * DIMN + lane * 4));
        float4 v2 = __ldcg((const float4*)(xs + (size_t)i2 * DIMN + lane * 4));
        float4 v3 = __ldcg((const float4*)(xs + (size_t)i3 * DIMN + lane * 4));
        a0.x += v0.x; a0.y += v0.y; a0.z += v0.z; a0.w += v0.w;
        a1.x += v1.x; a1.y += v1.y; a1.z += v1.z; a1.w += v1.w;
        a2.x += v2.x; a2.y += v2.y; a2.z += v2.z; a2.w += v2.w;
        a3.x += v3.x; a3.y += v3.y; a3.z += v3.z; a3.w += v3.w;
    }
    for (; e < s1; e++) {
        int i0 = __ldcs(&adj[e]);
        float4 v0 = __ldcg((const float4*)(xs + (size_t)i0 * DIMN + lane * 4));
        a0.x += v0.x; a0.y += v0.y; a0.z += v0.z; a0.w += v0.w;
    }
    a0.x += a1.x + a2.x + a3.x;
    a0.y += a1.y + a2.y + a3.y;
    a0.z += a1.z + a2.z + a3.z;
    a0.w += a1.w + a2.w + a3.w;
    int deg = s1 - s0;
    float inv = 1.0f / (float)(deg > 0 ? deg : 1);
    a0.x *= inv; a0.y *= inv; a0.z *= inv; a0.w *= inv;
    __stcs((float4*)(mean + (size_t)node * DIMN + lane * 4), a0);
}

// ---------------- mma.sync helpers ----------------
__device__ __forceinline__ uint32_t smem_u32(const void* p) {
    uint32_t a;
    asm("{ .reg .u64 t; cvta.to.shared.u64 t, %1; cvt.u32.u64 %0, t; }"
        : "=r"(a) : "l"(p));
    return a;
}
__device__ __forceinline__ void ldsm4(uint32_t* r, uint32_t addr) {
    asm volatile("ldmatrix.sync.aligned.m8n8.x4.shared.b16 {%0,%1,%2,%3}, [%4];"
                 : "=r"(r[0]), "=r"(r[1]), "=r"(r[2]), "=r"(r[3]) : "r"(addr));
}
__device__ __forceinline__ void mma16816(float* d, const uint32_t* a,
                                         uint32_t b0, uint32_t b1) {
    asm volatile(
        "mma.sync.aligned.m16n8k16.row.col.f32.bf16.bf16.f32 "
        "{%0,%1,%2,%3}, {%4,%5,%6,%7}, {%8,%9}, {%0,%1,%2,%3};"
        : "+f"(d[0]), "+f"(d[1]), "+f"(d[2]), "+f"(d[3])
        : "r"(a[0]), "r"(a[1]), "r"(a[2]), "r"(a[3]), "r"(b0), "r"(b1));
}
__device__ __forceinline__ void cpa16(uint32_t dst, const void* src) {
    asm volatile("cp.async.ca.shared.global [%0], [%1], 16;"
                 :: "r"(dst), "l"(src) : "memory");
}
#define CPA_COMMIT() asm volatile("cp.async.commit_group;" ::: "memory")
#define CPA_WAIT0()  asm volatile("cp.async.wait_group 0;" ::: "memory")

// ---------------- tensor-core GEMM (round-5 structure + .cs hints) ----------------
#define TSTRIDE 72   // elements; 144 bytes

__global__ void __launch_bounds__(256, 2)
k_gemm_mma(const float* __restrict__ xu, const float* __restrict__ xi,
           float* __restrict__ out_user, float* __restrict__ out_item,
           int NU, int NI, int blocksU)
{
    extern __shared__ __nv_bfloat16 smem[];
    __nv_bfloat16* Ah = smem;
    __nv_bfloat16* Al = Ah + 128 * TSTRIDE;
    __nv_bfloat16* Wh = Al + 128 * TSTRIDE;
    __nv_bfloat16* Wl = Wh + 128 * TSTRIDE;
    const uint32_t sAh = smem_u32(Ah);
    const uint32_t sAl = smem_u32(Al);
    const uint32_t sWh = smem_u32(Wh);
    const uint32_t sWl = smem_u32(Wl);

    int tid = threadIdx.x, w = tid >> 5, lane = tid & 31;
    bool isU = (int)blockIdx.x < blocksU;
    int bidl = isU ? blockIdx.x : (blockIdx.x - blocksU);
    int m0 = bidl * 128;
    int M  = isU ? NU : NI;
    int np = isU ? 2 : 3;
    const float* Ap[3];
    int wp[3];
    if (isU) { Ap[0] = g_meanR; Ap[1] = xu; Ap[2] = xu; wp[0] = 0; wp[1] = 1; wp[2] = 1; }
    else     { Ap[0] = g_meanB; Ap[1] = g_meanT; Ap[2] = xi; wp[0] = 2; wp[1] = 3; wp[2] = 4; }
    float* Cout = isU ? out_user : out_item;
    const float* bias = isU ? g_biasU : g_biasI;

    float acc[16][4];
    #pragma unroll
    for (int i = 0; i < 16; i++)
        #pragma unroll
        for (int j = 0; j < 4; j++) acc[i][j] = 0.f;

    int a_row = lane & 15;
    int a_kh  = (lane >> 4) << 3;
    int b_n   = (lane & 7) + ((lane >> 4) << 3);
    int b_kh  = ((lane >> 3) & 1) << 3;

    for (int p = 0; p < np; p++) {
        const float* A = Ap[p];
        const __nv_bfloat16* WHsrc = g_Wsp[wp[p]][0];
        const __nv_bfloat16* WLsrc = g_Wsp[wp[p]][1];
        for (int c = 0; c < 2; c++) {
            __syncthreads();   // protect previous iteration's smem reads
            // ---- W chunk via cp.async (overlaps with A convert below)
            #pragma unroll
            for (int it = 0; it < 4; it++) {
                int q = tid + it * 256;
                int n = q >> 3;
                int j = q & 7;
                cpa16(sWh + (n * TSTRIDE + j * 8) * 2, WHsrc + n * 128 + c * 64 + j * 8);
                cpa16(sWl + (n * TSTRIDE + j * 8) * 2, WLsrc + n * 128 + c * 64 + j * 8);
            }
            CPA_COMMIT();
            // ---- load & split A chunk [128 m x 64 k] (read-once: .cs)
            #pragma unroll
            for (int it = 0; it < 8; it++) {
                int q = tid + it * 256;
                int row = q >> 4;
                int k4  = (q & 15) << 2;
                int grow = m0 + row;
                float4 v = make_float4(0.f, 0.f, 0.f, 0.f);
                if (grow < M) v = __ldcs((const float4*)(A + (size_t)grow * DIMN + c * 64 + k4));
                __nv_bfloat16 h0 = __float2bfloat16_rn(v.x);
                __nv_bfloat16 h1 = __float2bfloat16_rn(v.y);
                __nv_bfloat16 h2 = __float2bfloat16_rn(v.z);
                __nv_bfloat16 h3 = __float2bfloat16_rn(v.w);
                ushort4 uh = make_ushort4(__bfloat16_as_ushort(h0), __bfloat16_as_ushort(h1),
                                          __bfloat16_as_ushort(h2), __bfloat16_as_ushort(h3));
                __nv_bfloat16 l0 = __float2bfloat16_rn(v.x - __bfloat162float(h0));
                __nv_bfloat16 l1 = __float2bfloat16_rn(v.y - __bfloat162float(h1));
                __nv_bfloat16 l2 = __float2bfloat16_rn(v.z - __bfloat162float(h2));
                __nv_bfloat16 l3 = __float2bfloat16_rn(v.w - __bfloat162float(h3));
                ushort4 ul = make_ushort4(__bfloat16_as_ushort(l0), __bfloat16_as_ushort(l1),
                                          __bfloat16_as_ushort(l2), __bfloat16_as_ushort(l3));
                *(ushort4*)(Ah + row * TSTRIDE + k4) = uh;
                *(ushort4*)(Al + row * TSTRIDE + k4) = ul;
            }
            CPA_WAIT0();
            __syncthreads();
            // ---- compute: warp w owns rows [w*16, w*16+16)
            #pragma unroll
            for (int ks = 0; ks < 4; ks++) {
                uint32_t aH[4], aL[4];
                uint32_t aoff = (w * 16 + a_row) * (TSTRIDE * 2) + (ks * 16 + a_kh) * 2;
                ldsm4(aH, sAh + aoff);
                ldsm4(aL, sAl + aoff);
                #pragma unroll
                for (int nt = 0; nt < 8; nt++) {
                    uint32_t bH[4], bL[4];
                    uint32_t boff = (nt * 16 + b_n) * (TSTRIDE * 2) + (ks * 16 + b_kh) * 2;
                    ldsm4(bH, sWh + boff);
                    ldsm4(bL, sWl + boff);
                    mma16816(acc[nt * 2],     aH, bH[0], bH[1]);
                    mma16816(acc[nt * 2 + 1], aH, bH[2], bH[3]);
                    mma16816(acc[nt * 2],     aH, bL[0], bL[1]);
                    mma16816(acc[nt * 2 + 1], aH, bL[2], bL[3]);
                    mma16816(acc[nt * 2],     aL, bH[0], bH[1]);
                    mma16816(acc[nt * 2 + 1], aL, bH[2], bH[3]);
                }
            }
        }
    }

    // ---- epilogue (streaming stores)
    int row0 = m0 + w * 16 + (lane >> 2);
    int row1 = row0 + 8;
    int ncol = (lane & 3) * 2;
    #pragma unroll
    for (int t8 = 0; t8 < 16; t8++) {
        int n = t8 * 8 + ncol;
        float2 bv = *(const float2*)(bias + n);
        if (row0 < M) {
            float2 o = make_float2(acc[t8][0] + bv.x, acc[t8][1] + bv.y);
            __stcs((float2*)(Cout + (size_t)row0 * DIMN + n), o);
        }
        if (row1 < M) {
            float2 o = make_float2(acc[t8][2] + bv.x, acc[t8][3] + bv.y);
            __stcs((float2*)(Cout + (size_t)row1 * DIMN + n), o);
        }
    }
}

// ---------------- launch ----------------
extern "C" void kernel_launch(void* const* d_in, const int* in_sizes, int n_in,
                              void* d_out, int out_size) {
    const float* xu  = (const float*)d_in[0];
    const float* xi  = (const float*)d_in[1];
    const float* xt  = (const float*)d_in[2];
    const int*   eb  = (const int*)d_in[3];
    const int*   er  = (const int*)d_in[4];
    const int*   et  = (const int*)d_in[5];
    const float* WlB = (const float*)d_in[6];
    const float* WrB = (const float*)d_in[7];
    const float* bB  = (const float*)d_in[8];
    const float* WlR = (const float*)d_in[9];
    const float* WrR = (const float*)d_in[10];
    const float* bR  = (const float*)d_in[11];
    const float* WlT = (const float*)d_in[12];
    const float* WrT = (const float*)d_in[13];
    const float* bT  = (const float*)d_in[14];

    int NU = in_sizes[0] / DIMN;
    int NI = in_sizes[1] / DIMN;
    int EB = in_sizes[3] / 2;
    int ER = in_sizes[4] / 2;
    int ET = in_sizes[5] / 2;

    float* out_user = (float*)d_out;
    float* out_item = (float*)d_out + (size_t)NU * DIMN;

    int Etot = EB + ER + ET;

    k_init<<<(3 * (NU_MAX + 1) + 255) / 256, 256>>>(WlR, WrR, WlB, WlT, WrB, WrT,
                                                    bR, bB, bT);
    k_hist3<<<(Etot / 2 + 256) / 256, 256>>>(eb + EB, er + ER, et + ET, EB, ER, ET);
    k_scan<<<3, 1024>>>(NI, NU, NI);
    k_fill3<<<(Etot / 2 + 256) / 256, 256>>>(eb, er, et, EB, ER, ET);

    int totalNodes = NI + NU + NI;
    k_agg3<<<(totalNodes * 32 + 255) / 256, 256>>>(xu, xi, xt, NU, NI);

    const int SMEM_BYTES = 4 * 128 * TSTRIDE * 2;   // 73728
    cudaFuncSetAttribute(k_gemm_mma, cudaFuncAttributeMaxDynamicSharedMemorySize, SMEM_BYTES);
    int blocksU = (NU + 127) / 128;
    int blocksI = (NI + 127) / 128;
    k_gemm_mma<<<blocksU + blocksI, 256, SMEM_BYTES>>>(xu, xi, out_user, out_item,
                                                       NU, NI, blocksU);
}

// round 8
// speedup vs baseline: 1.0601x; 1.0601x over previous
#include <cuda_runtime.h>
#include <cuda_bf16.h>
#include <cstddef>
#include <cstdint>

#define NU_MAX 100000
#define NI_MAX 100000
#define E_MAX  1000000
#define DIMN   128

// ---------------- scratch (static __device__, no allocation) ----------------
__device__ int   g_cnt[3][NU_MAX + 1];
__device__ int   g_off[3][NU_MAX + 1];
__device__ int   g_cur[3][NU_MAX];
__device__ int   g_adj[3][E_MAX];
__device__ float g_meanB[(size_t)NI_MAX * DIMN];
__device__ float g_meanR[(size_t)NU_MAX * DIMN];
__device__ float g_meanT[(size_t)NI_MAX * DIMN];

// split + transposed weights: [panel][half hi/lo][n*128+k] bf16
__device__ __align__(16) __nv_bfloat16 g_Wsp[5][2][DIMN * DIMN];
__device__ __align__(16) float g_biasU[DIMN];
__device__ __align__(16) float g_biasI[DIMN];

// ---------------- init: zero counters + weight prep (merged) ----------------
__global__ void k_init(const float* __restrict__ WlR, const float* __restrict__ WrR,
                       const float* __restrict__ WlB, const float* __restrict__ WlT,
                       const float* __restrict__ WrB, const float* __restrict__ WrT,
                       const float* __restrict__ bR, const float* __restrict__ bB,
                       const float* __restrict__ bT) {
    int i = blockIdx.x * blockDim.x + threadIdx.x;
    const int total = 3 * (NU_MAX + 1);
    if (i < total) ((int*)g_cnt)[i] = 0;
    if (i < 5 * 16384) {
        int panel = i >> 14;
        int e = i & 16383;
        int k = e >> 7;
        int n = e & 127;
        float v;
        switch (panel) {
            case 0:  v = WlR[k * 128 + n]; break;
            case 1:  v = WrR[k * 128 + n]; break;
            case 2:  v = 0.5f * WlB[k * 128 + n]; break;
            case 3:  v = 0.5f * WlT[k * 128 + n]; break;
            default: v = 0.5f * (WrB[k * 128 + n] + WrT[k * 128 + n]);
        }
        __nv_bfloat16 h = __float2bfloat16_rn(v);
        __nv_bfloat16 l = __float2bfloat16_rn(v - __bfloat162float(h));
        g_Wsp[panel][0][n * 128 + k] = h;
        g_Wsp[panel][1][n * 128 + k] = l;
    }
    if (i < DIMN) {
        g_biasU[i] = bR[i];
        g_biasI[i] = 0.5f * (bB[i] + bT[i]);
    }
}

// ---------------- CSR build (4 edges per thread for ILP) ----------------
__global__ void k_hist3(const int* __restrict__ db, const int* __restrict__ dr,
                        const int* __restrict__ dt, int EB, int ER, int ET) {
    int t = blockIdx.x * blockDim.x + threadIdx.x;
    #pragma unroll
    for (int j = 0; j < 4; j++) {
        int e = t * 4 + j;
        if (e < EB) atomicAdd(&g_cnt[0][db[e]], 1);
        else if (e < EB + ER) atomicAdd(&g_cnt[1][dr[e - EB]], 1);
        else if (e < EB + ER + ET) atomicAdd(&g_cnt[2][dt[e - EB - ER]], 1);
    }
}

// warp-shuffle based exclusive scan; 3 blocks (one per relation), 1024 threads
__global__ void k_scan(int n0, int n1, int n2) {
    int rel = blockIdx.x;
    int n = (rel == 0) ? n0 : (rel == 1) ? n1 : n2;
    int lane = threadIdx.x & 31, wid = threadIdx.x >> 5;
    __shared__ int wsum[32];
    __shared__ int carry;
    if (threadIdx.x == 0) carry = 0;
    __syncthreads();
    for (int base = 0; base < n; base += 1024) {
        int i = base + threadIdx.x;
        int v = (i < n) ? g_cnt[rel][i] : 0;
        int s = v;
        #pragma unroll
        for (int d = 1; d < 32; d <<= 1) {
            int t = __shfl_up_sync(0xFFFFFFFFu, s, d);
            if (lane >= d) s += t;
        }
        if (lane == 31) wsum[wid] = s;
        __syncthreads();
        if (wid == 0) {
            int w = wsum[lane];
            #pragma unroll
            for (int d = 1; d < 32; d <<= 1) {
                int t = __shfl_up_sync(0xFFFFFFFFu, w, d);
                if (lane >= d) w += t;
            }
            wsum[lane] = w;
        }
        __syncthreads();
        int woff = (wid > 0) ? wsum[wid - 1] : 0;
        int c = carry;
        int excl = c + woff + s - v;
        if (i < n) { g_off[rel][i] = excl; g_cur[rel][i] = excl; }
        int tot = wsum[31];
        __syncthreads();
        if (threadIdx.x == 0) carry = c + tot;
        __syncthreads();
    }
    if (threadIdx.x == 0) g_off[rel][n] = carry;
}

__global__ void k_fill3(const int* __restrict__ eb, const int* __restrict__ er,
                        const int* __restrict__ et, int EB, int ER, int ET) {
    int t = blockIdx.x * blockDim.x + threadIdx.x;
    #pragma unroll
    for (int j = 0; j < 4; j++) {
        int e = t * 4 + j;
        int rel, idx;
        const int* ei;
        int E;
        if (e < EB) { rel = 0; idx = e; ei = eb; E = EB; }
        else if (e < EB + ER) { rel = 1; idx = e - EB; ei = er; E = ER; }
        else if (e < EB + ER + ET) { rel = 2; idx = e - EB - ER; ei = et; E = ET; }
        else continue;
        int d = ei[E + idx];
        int s = ei[idx];
        int p = atomicAdd(&g_cur[rel][d], 1);
        g_adj[rel][p] = s;
    }
}

// ---------------- mean aggregation: warp/node, index-prefetch pipelined ----------------
__global__ void k_agg3(const float* __restrict__ xu, const float* __restrict__ xi,
                       const float* __restrict__ xt, int NU, int NI) {
    int w = (blockIdx.x * blockDim.x + threadIdx.x) >> 5;
    int lane = threadIdx.x & 31;
    int rel, node;
    const float* xs;
    float* mean;
    if (w < NI) { rel = 0; node = w; xs = xu; mean = g_meanB; }
    else if (w < NI + NU) { rel = 1; node = w - NI; xs = xi; mean = g_meanR; }
    else if (w < NI + NU + NI) { rel = 2; node = w - NI - NU; xs = xt; mean = g_meanT; }
    else return;

    const int* __restrict__ adj = g_adj[rel];
    int s0 = g_off[rel][node], s1 = g_off[rel][node + 1];
    int deg = s1 - s0;
    int nfull = deg & ~3;
    int end4 = s0 + nfull;

    float4 a0 = make_float4(0.f, 0.f, 0.f, 0.f);
    float4 a1 = make_float4(0.f, 0.f, 0.f, 0.f);
    float4 a2 = make_float4(0.f, 0.f, 0.f, 0.f);
    float4 a3 = make_float4(0.f, 0.f, 0.f, 0.f);

    int i0 = 0, i1 = 0, i2 = 0, i3 = 0;
    if (nfull) {
        i0 = __ldg(&adj[s0]);
        i1 = __ldg(&adj[s0 + 1]);
        i2 = __ldg(&adj[s0 + 2]);
        i3 = __ldg(&adj[s0 + 3]);
    }
    for (int e = s0; e < end4; ) {
        // issue row gathers for current indices
        float4 v0 = *(const float4*)(xs + (size_t)i0 * DIMN + lane * 4);
        float4 v1 = *(const float4*)(xs + (size_t)i1 * DIMN + lane * 4);
        float4 v2 = *(const float4*)(xs + (size_t)i2 * DIMN + lane * 4);
        float4 v3 = *(const float4*)(xs + (size_t)i3 * DIMN + lane * 4);
        e += 4;
        // prefetch next iteration's indices (overlaps with row-load latency)
        if (e < end4) {
            i0 = __ldg(&adj[e]);
            i1 = __ldg(&adj[e + 1]);
            i2 = __ldg(&adj[e + 2]);
            i3 = __ldg(&adj[e + 3]);
        }
        a0.x += v0.x; a0.y += v0.y; a0.z += v0.z; a0.w += v0.w;
        a1.x += v1.x; a1.y += v1.y; a1.z += v1.z; a1.w += v1.w;
        a2.x += v2.x; a2.y += v2.y; a2.z += v2.z; a2.w += v2.w;
        a3.x += v3.x; a3.y += v3.y; a3.z += v3.z; a3.w += v3.w;
    }
    for (int e = end4; e < s1; e++) {
        int a = __ldg(&adj[e]);
        float4 v0 = *(const float4*)(xs + (size_t)a * DIMN + lane * 4);
        a0.x += v0.x; a0.y += v0.y; a0.z += v0.z; a0.w += v0.w;
    }
    a0.x += a1.x + a2.x + a3.x;
    a0.y += a1.y + a2.y + a3.y;
    a0.z += a1.z + a2.z + a3.z;
    a0.w += a1.w + a2.w + a3.w;
    float inv = 1.0f / (float)(deg > 0 ? deg : 1);
    a0.x *= inv; a0.y *= inv; a0.z *= inv; a0.w *= inv;
    *(float4*)(mean + (size_t)node * DIMN + lane * 4) = a0;
}

// ---------------- mma.sync helpers ----------------
__device__ __forceinline__ uint32_t smem_u32(const void* p) {
    uint32_t a;
    asm("{ .reg .u64 t; cvta.to.shared.u64 t, %1; cvt.u32.u64 %0, t; }"
        : "=r"(a) : "l"(p));
    return a;
}
__device__ __forceinline__ void ldsm4(uint32_t* r, uint32_t addr) {
    asm volatile("ldmatrix.sync.aligned.m8n8.x4.shared.b16 {%0,%1,%2,%3}, [%4];"
                 : "=r"(r[0]), "=r"(r[1]), "=r"(r[2]), "=r"(r[3]) : "r"(addr));
}
__device__ __forceinline__ void mma16816(float* d, const uint32_t* a,
                                         uint32_t b0, uint32_t b1) {
    asm volatile(
        "mma.sync.aligned.m16n8k16.row.col.f32.bf16.bf16.f32 "
        "{%0,%1,%2,%3}, {%4,%5,%6,%7}, {%8,%9}, {%0,%1,%2,%3};"
        : "+f"(d[0]), "+f"(d[1]), "+f"(d[2]), "+f"(d[3])
        : "r"(a[0]), "r"(a[1]), "r"(a[2]), "r"(a[3]), "r"(b0), "r"(b1));
}
__device__ __forceinline__ void cpa16(uint32_t dst, const void* src) {
    asm volatile("cp.async.ca.shared.global [%0], [%1], 16;"
                 :: "r"(dst), "l"(src) : "memory");
}
#define CPA_COMMIT() asm volatile("cp.async.commit_group;" ::: "memory")
#define CPA_WAIT0()  asm volatile("cp.async.wait_group 0;" ::: "memory")

// ---------------- tensor-core GEMM (round-5 structure, exact) ----------------
#define TSTRIDE 72   // elements; 144 bytes

__global__ void __launch_bounds__(256, 2)
k_gemm_mma(const float* __restrict__ xu, const float* __restrict__ xi,
           float* __restrict__ out_user, float* __restrict__ out_item,
           int NU, int NI, int blocksU)
{
    extern __shared__ __nv_bfloat16 smem[];
    __nv_bfloat16* Ah = smem;
    __nv_bfloat16* Al = Ah + 128 * TSTRIDE;
    __nv_bfloat16* Wh = Al + 128 * TSTRIDE;
    __nv_bfloat16* Wl = Wh + 128 * TSTRIDE;
    const uint32_t sAh = smem_u32(Ah);
    const uint32_t sAl = smem_u32(Al);
    const uint32_t sWh = smem_u32(Wh);
    const uint32_t sWl = smem_u32(Wl);

    int tid = threadIdx.x, w = tid >> 5, lane = tid & 31;
    bool isU = (int)blockIdx.x < blocksU;
    int bidl = isU ? blockIdx.x : (blockIdx.x - blocksU);
    int m0 = bidl * 128;
    int M  = isU ? NU : NI;
    int np = isU ? 2 : 3;
    const float* Ap[3];
    int wp[3];
    if (isU) { Ap[0] = g_meanR; Ap[1] = xu; Ap[2] = xu; wp[0] = 0; wp[1] = 1; wp[2] = 1; }
    else     { Ap[0] = g_meanB; Ap[1] = g_meanT; Ap[2] = xi; wp[0] = 2; wp[1] = 3; wp[2] = 4; }
    float* Cout = isU ? out_user : out_item;
    const float* bias = isU ? g_biasU : g_biasI;

    float acc[16][4];
    #pragma unroll
    for (int i = 0; i < 16; i++)
        #pragma unroll
        for (int j = 0; j < 4; j++) acc[i][j] = 0.f;

    int a_row = lane & 15;
    int a_kh  = (lane >> 4) << 3;
    int b_n   = (lane & 7) + ((lane >> 4) << 3);
    int b_kh  = ((lane >> 3) & 1) << 3;

    for (int p = 0; p < np; p++) {
        const float* A = Ap[p];
        const __nv_bfloat16* WHsrc = g_Wsp[wp[p]][0];
        const __nv_bfloat16* WLsrc = g_Wsp[wp[p]][1];
        for (int c = 0; c < 2; c++) {
            __syncthreads();   // protect previous iteration's smem reads
            // ---- W chunk via cp.async (overlaps with A convert below)
            #pragma unroll
            for (int it = 0; it < 4; it++) {
                int q = tid + it * 256;
                int n = q >> 3;
                int j = q & 7;
                cpa16(sWh + (n * TSTRIDE + j * 8) * 2, WHsrc + n * 128 + c * 64 + j * 8);
                cpa16(sWl + (n * TSTRIDE + j * 8) * 2, WLsrc + n * 128 + c * 64 + j * 8);
            }
            CPA_COMMIT();
            // ---- load & split A chunk [128 m x 64 k]
            #pragma unroll
            for (int it = 0; it < 8; it++) {
                int q = tid + it * 256;
                int row = q >> 4;
                int k4  = (q & 15) << 2;
                int grow = m0 + row;
                float4 v = make_float4(0.f, 0.f, 0.f, 0.f);
                if (grow < M) v = *(const float4*)(A + (size_t)grow * DIMN + c * 64 + k4);
                __nv_bfloat16 h0 = __float2bfloat16_rn(v.x);
                __nv_bfloat16 h1 = __float2bfloat16_rn(v.y);
                __nv_bfloat16 h2 = __float2bfloat16_rn(v.z);
                __nv_bfloat16 h3 = __float2bfloat16_rn(v.w);
                ushort4 uh = make_ushort4(__bfloat16_as_ushort(h0), __bfloat16_as_ushort(h1),
                                          __bfloat16_as_ushort(h2), __bfloat16_as_ushort(h3));
                __nv_bfloat16 l0 = __float2bfloat16_rn(v.x - __bfloat162float(h0));
                __nv_bfloat16 l1 = __float2bfloat16_rn(v.y - __bfloat162float(h1));
                __nv_bfloat16 l2 = __float2bfloat16_rn(v.z - __bfloat162float(h2));
                __nv_bfloat16 l3 = __float2bfloat16_rn(v.w - __bfloat162float(h3));
                ushort4 ul = make_ushort4(__bfloat16_as_ushort(l0), __bfloat16_as_ushort(l1),
                                          __bfloat16_as_ushort(l2), __bfloat16_as_ushort(l3));
                *(ushort4*)(Ah + row * TSTRIDE + k4) = uh;
                *(ushort4*)(Al + row * TSTRIDE + k4) = ul;
            }
            CPA_WAIT0();
            __syncthreads();
            // ---- compute: warp w owns rows [w*16, w*16+16)
            #pragma unroll
            for (int ks = 0; ks < 4; ks++) {
                uint32_t aH[4], aL[4];
                uint32_t aoff = (w * 16 + a_row) * (TSTRIDE * 2) + (ks * 16 + a_kh) * 2;
                ldsm4(aH, sAh + aoff);
                ldsm4(aL, sAl + aoff);
                #pragma unroll
                for (int nt = 0; nt < 8; nt++) {
                    uint32_t bH[4], bL[4];
                    uint32_t boff = (nt * 16 + b_n) * (TSTRIDE * 2) + (ks * 16 + b_kh) * 2;
                    ldsm4(bH, sWh + boff);
                    ldsm4(bL, sWl + boff);
                    mma16816(acc[nt * 2],     aH, bH[0], bH[1]);
                    mma16816(acc[nt * 2 + 1], aH, bH[2], bH[3]);
                    mma16816(acc[nt * 2],     aH, bL[0], bL[1]);
                    mma16816(acc[nt * 2 + 1], aH, bL[2], bL[3]);
                    mma16816(acc[nt * 2],     aL, bH[0], bH[1]);
                    mma16816(acc[nt * 2 + 1], aL, bH[2], bH[3]);
                }
            }
        }
    }

    // ---- epilogue
    int row0 = m0 + w * 16 + (lane >> 2);
    int row1 = row0 + 8;
    int ncol = (lane & 3) * 2;
    #pragma unroll
    for (int t8 = 0; t8 < 16; t8++) {
        int n = t8 * 8 + ncol;
        float2 bv = *(const float2*)(bias + n);
        if (row0 < M) {
            float2 o = make_float2(acc[t8][0] + bv.x, acc[t8][1] + bv.y);
            *(float2*)(Cout + (size_t)row0 * DIMN + n) = o;
        }
        if (row1 < M) {
            float2 o = make_float2(acc[t8][2] + bv.x, acc[t8][3] + bv.y);
            *(float2*)(Cout + (size_t)row1 * DIMN + n) = o;
        }
    }
}

// ---------------- launch ----------------
extern "C" void kernel_launch(void* const* d_in, const int* in_sizes, int n_in,
                              void* d_out, int out_size) {
    const float* xu  = (const float*)d_in[0];
    const float* xi  = (const float*)d_in[1];
    const float* xt  = (const float*)d_in[2];
    const int*   eb  = (const int*)d_in[3];
    const int*   er  = (const int*)d_in[4];
    const int*   et  = (const int*)d_in[5];
    const float* WlB = (const float*)d_in[6];
    const float* WrB = (const float*)d_in[7];
    const float* bB  = (const float*)d_in[8];
    const float* WlR = (const float*)d_in[9];
    const float* WrR = (const float*)d_in[10];
    const float* bR  = (const float*)d_in[11];
    const float* WlT = (const float*)d_in[12];
    const float* WrT = (const float*)d_in[13];
    const float* bT  = (const float*)d_in[14];

    int NU = in_sizes[0] / DIMN;
    int NI = in_sizes[1] / DIMN;
    int EB = in_sizes[3] / 2;
    int ER = in_sizes[4] / 2;
    int ET = in_sizes[5] / 2;

    float* out_user = (float*)d_out;
    float* out_item = (float*)d_out + (size_t)NU * DIMN;

    int Etot = EB + ER + ET;

    k_init<<<(3 * (NU_MAX + 1) + 255) / 256, 256>>>(WlR, WrR, WlB, WlT, WrB, WrT,
                                                    bR, bB, bT);
    k_hist3<<<(Etot / 4 + 256) / 256, 256>>>(eb + EB, er + ER, et + ET, EB, ER, ET);
    k_scan<<<3, 1024>>>(NI, NU, NI);
    k_fill3<<<(Etot / 4 + 256) / 256, 256>>>(eb, er, et, EB, ER, ET);

    int totalNodes = NI + NU + NI;
    k_agg3<<<(totalNodes * 32 + 255) / 256, 256>>>(xu, xi, xt, NU, NI);

    const int SMEM_BYTES = 4 * 128 * TSTRIDE * 2;   // 73728
    cudaFuncSetAttribute(k_gemm_mma, cudaFuncAttributeMaxDynamicSharedMemorySize, SMEM_BYTES);
    int blocksU = (NU + 127) / 128;
    int blocksI = (NI + 127) / 128;
    k_gemm_mma<<<blocksU + blocksI, 256, SMEM_BYTES>>>(xu, xi, out_user, out_item,
                                                       NU, NI, blocksU);
}

// round 9
// speedup vs baseline: 1.1025x; 1.0400x over previous
#include <cuda_runtime.h>
#include <cuda_bf16.h>
#include <cstddef>
#include <cstdint>

#define NU_MAX 100000
#define NI_MAX 100000
#define E_MAX  1000000
#define DIMN   128

// ---------------- scratch (static __device__, no allocation) ----------------
__device__ int   g_cnt[3][NU_MAX + 1];
__device__ int   g_off[3][NU_MAX + 1];
__device__ int   g_cur[3][NU_MAX];
__device__ int   g_adj[3][E_MAX];
__device__ float g_meanB[(size_t)NI_MAX * DIMN];
__device__ float g_meanR[(size_t)NU_MAX * DIMN];
__device__ float g_meanT[(size_t)NI_MAX * DIMN];

// split + transposed weights: [panel][half hi/lo][n*128+k] bf16
__device__ __align__(16) __nv_bfloat16 g_Wsp[5][2][DIMN * DIMN];
__device__ __align__(16) float g_biasU[DIMN];
__device__ __align__(16) float g_biasI[DIMN];

// ---------------- init: zero counters + weight prep (merged) ----------------
__global__ void k_init(const float* __restrict__ WlR, const float* __restrict__ WrR,
                       const float* __restrict__ WlB, const float* __restrict__ WlT,
                       const float* __restrict__ WrB, const float* __restrict__ WrT,
                       const float* __restrict__ bR, const float* __restrict__ bB,
                       const float* __restrict__ bT) {
    int i = blockIdx.x * blockDim.x + threadIdx.x;
    const int total = 3 * (NU_MAX + 1);
    if (i < total) ((int*)g_cnt)[i] = 0;
    if (i < 5 * 16384) {
        int panel = i >> 14;
        int e = i & 16383;
        int k = e >> 7;
        int n = e & 127;
        float v;
        switch (panel) {
            case 0:  v = WlR[k * 128 + n]; break;
            case 1:  v = WrR[k * 128 + n]; break;
            case 2:  v = 0.5f * WlB[k * 128 + n]; break;
            case 3:  v = 0.5f * WlT[k * 128 + n]; break;
            default: v = 0.5f * (WrB[k * 128 + n] + WrT[k * 128 + n]);
        }
        __nv_bfloat16 h = __float2bfloat16_rn(v);
        __nv_bfloat16 l = __float2bfloat16_rn(v - __bfloat162float(h));
        g_Wsp[panel][0][n * 128 + k] = h;
        g_Wsp[panel][1][n * 128 + k] = l;
    }
    if (i < DIMN) {
        g_biasU[i] = bR[i];
        g_biasI[i] = 0.5f * (bB[i] + bT[i]);
    }
}

// ---------------- CSR build (round-5 config: 2 edges/thread) ----------------
__global__ void k_hist3(const int* __restrict__ db, const int* __restrict__ dr,
                        const int* __restrict__ dt, int EB, int ER, int ET) {
    int t = blockIdx.x * blockDim.x + threadIdx.x;
    #pragma unroll
    for (int j = 0; j < 2; j++) {
        int e = t * 2 + j;
        if (e < EB) atomicAdd(&g_cnt[0][db[e]], 1);
        else if (e < EB + ER) atomicAdd(&g_cnt[1][dr[e - EB]], 1);
        else if (e < EB + ER + ET) atomicAdd(&g_cnt[2][dt[e - EB - ER]], 1);
    }
}

// warp-shuffle based exclusive scan; 3 blocks (one per relation), 1024 threads
__global__ void k_scan(int n0, int n1, int n2) {
    int rel = blockIdx.x;
    int n = (rel == 0) ? n0 : (rel == 1) ? n1 : n2;
    int lane = threadIdx.x & 31, wid = threadIdx.x >> 5;
    __shared__ int wsum[32];
    __shared__ int carry;
    if (threadIdx.x == 0) carry = 0;
    __syncthreads();
    for (int base = 0; base < n; base += 1024) {
        int i = base + threadIdx.x;
        int v = (i < n) ? g_cnt[rel][i] : 0;
        int s = v;
        #pragma unroll
        for (int d = 1; d < 32; d <<= 1) {
            int t = __shfl_up_sync(0xFFFFFFFFu, s, d);
            if (lane >= d) s += t;
        }
        if (lane == 31) wsum[wid] = s;
        __syncthreads();
        if (wid == 0) {
            int w = wsum[lane];
            #pragma unroll
            for (int d = 1; d < 32; d <<= 1) {
                int t = __shfl_up_sync(0xFFFFFFFFu, w, d);
                if (lane >= d) w += t;
            }
            wsum[lane] = w;
        }
        __syncthreads();
        int woff = (wid > 0) ? wsum[wid - 1] : 0;
        int c = carry;
        int excl = c + woff + s - v;
        if (i < n) { g_off[rel][i] = excl; g_cur[rel][i] = excl; }
        int tot = wsum[31];
        __syncthreads();
        if (threadIdx.x == 0) carry = c + tot;
        __syncthreads();
    }
    if (threadIdx.x == 0) g_off[rel][n] = carry;
}

__global__ void k_fill3(const int* __restrict__ eb, const int* __restrict__ er,
                        const int* __restrict__ et, int EB, int ER, int ET) {
    int t = blockIdx.x * blockDim.x + threadIdx.x;
    #pragma unroll
    for (int j = 0; j < 2; j++) {
        int e = t * 2 + j;
        int rel, idx;
        const int* ei;
        int E;
        if (e < EB) { rel = 0; idx = e; ei = eb; E = EB; }
        else if (e < EB + ER) { rel = 1; idx = e - EB; ei = er; E = ER; }
        else if (e < EB + ER + ET) { rel = 2; idx = e - EB - ER; ei = et; E = ET; }
        else continue;
        int d = ei[E + idx];
        int s = ei[idx];
        int p = atomicAdd(&g_cur[rel][d], 1);
        g_adj[rel][p] = s;
    }
}

// ---------------- mean aggregation: one warp per dst node, unroll-4 (round-5) ----------------
__global__ void k_agg3(const float* __restrict__ xu, const float* __restrict__ xi,
                       const float* __restrict__ xt, int NU, int NI) {
    int w = (blockIdx.x * blockDim.x + threadIdx.x) >> 5;
    int lane = threadIdx.x & 31;
    int rel, node;
    const float* xs;
    float* mean;
    if (w < NI) { rel = 0; node = w; xs = xu; mean = g_meanB; }
    else if (w < NI + NU) { rel = 1; node = w - NI; xs = xi; mean = g_meanR; }
    else if (w < NI + NU + NI) { rel = 2; node = w - NI - NU; xs = xt; mean = g_meanT; }
    else return;

    const int* __restrict__ adj = g_adj[rel];
    int s0 = g_off[rel][node], s1 = g_off[rel][node + 1];
    float4 a0 = make_float4(0.f, 0.f, 0.f, 0.f);
    float4 a1 = make_float4(0.f, 0.f, 0.f, 0.f);
    float4 a2 = make_float4(0.f, 0.f, 0.f, 0.f);
    float4 a3 = make_float4(0.f, 0.f, 0.f, 0.f);
    int e = s0;
    for (; e + 3 < s1; e += 4) {
        int i0 = __ldg(&adj[e]);
        int i1 = __ldg(&adj[e + 1]);
        int i2 = __ldg(&adj[e + 2]);
        int i3 = __ldg(&adj[e + 3]);
        float4 v0 = *(const float4*)(xs + (size_t)i0 * DIMN + lane * 4);
        float4 v1 = *(const float4*)(xs + (size_t)i1 * DIMN + lane * 4);
        float4 v2 = *(const float4*)(xs + (size_t)i2 * DIMN + lane * 4);
        float4 v3 = *(const float4*)(xs + (size_t)i3 * DIMN + lane * 4);
        a0.x += v0.x; a0.y += v0.y; a0.z += v0.z; a0.w += v0.w;
        a1.x += v1.x; a1.y += v1.y; a1.z += v1.z; a1.w += v1.w;
        a2.x += v2.x; a2.y += v2.y; a2.z += v2.z; a2.w += v2.w;
        a3.x += v3.x; a3.y += v3.y; a3.z += v3.z; a3.w += v3.w;
    }
    for (; e < s1; e++) {
        int i0 = __ldg(&adj[e]);
        float4 v0 = *(const float4*)(xs + (size_t)i0 * DIMN + lane * 4);
        a0.x += v0.x; a0.y += v0.y; a0.z += v0.z; a0.w += v0.w;
    }
    a0.x += a1.x + a2.x + a3.x;
    a0.y += a1.y + a2.y + a3.y;
    a0.z += a1.z + a2.z + a3.z;
    a0.w += a1.w + a2.w + a3.w;
    int deg = s1 - s0;
    float inv = 1.0f / (float)(deg > 0 ? deg : 1);
    a0.x *= inv; a0.y *= inv; a0.z *= inv; a0.w *= inv;
    *(float4*)(mean + (size_t)node * DIMN + lane * 4) = a0;
}

// ---------------- mma.sync helpers ----------------
__device__ __forceinline__ uint32_t smem_u32(const void* p) {
    uint32_t a;
    asm("{ .reg .u64 t; cvta.to.shared.u64 t, %1; cvt.u32.u64 %0, t; }"
        : "=r"(a) : "l"(p));
    return a;
}
__device__ __forceinline__ void ldsm4(uint32_t* r, uint32_t addr) {
    asm volatile("ldmatrix.sync.aligned.m8n8.x4.shared.b16 {%0,%1,%2,%3}, [%4];"
                 : "=r"(r[0]), "=r"(r[1]), "=r"(r[2]), "=r"(r[3]) : "r"(addr));
}
__device__ __forceinline__ void mma16816(float* d, const uint32_t* a,
                                         uint32_t b0, uint32_t b1) {
    asm volatile(
        "mma.sync.aligned.m16n8k16.row.col.f32.bf16.bf16.f32 "
        "{%0,%1,%2,%3}, {%4,%5,%6,%7}, {%8,%9}, {%0,%1,%2,%3};"
        : "+f"(d[0]), "+f"(d[1]), "+f"(d[2]), "+f"(d[3])
        : "r"(a[0]), "r"(a[1]), "r"(a[2]), "r"(a[3]), "r"(b0), "r"(b1));
}
__device__ __forceinline__ void cpa16(uint32_t dst, const void* src) {
    asm volatile("cp.async.ca.shared.global [%0], [%1], 16;"
                 :: "r"(dst), "l"(src) : "memory");
}
#define CPA_COMMIT() asm volatile("cp.async.commit_group;" ::: "memory")
#define CPA_WAIT0()  asm volatile("cp.async.wait_group 0;" ::: "memory")

// ---------------- tensor-core GEMM: 2D warp tiling (4 m-strips x 2 n-halves) ----------------
#define TSTRIDE 72   // elements; 144 bytes

__global__ void __launch_bounds__(256, 2)
k_gemm_mma(const float* __restrict__ xu, const float* __restrict__ xi,
           float* __restrict__ out_user, float* __restrict__ out_item,
           int NU, int NI, int blocksU)
{
    extern __shared__ __nv_bfloat16 smem[];
    __nv_bfloat16* Ah = smem;
    __nv_bfloat16* Al = Ah + 128 * TSTRIDE;
    __nv_bfloat16* Wh = Al + 128 * TSTRIDE;
    __nv_bfloat16* Wl = Wh + 128 * TSTRIDE;
    const uint32_t sAh = smem_u32(Ah);
    const uint32_t sAl = smem_u32(Al);
    const uint32_t sWh = smem_u32(Wh);
    const uint32_t sWl = smem_u32(Wl);

    int tid = threadIdx.x, w = tid >> 5, lane = tid & 31;
    int wm = w & 3;          // m-strip: rows [wm*32, wm*32+32)
    int wn = w >> 2;         // n-half:  cols [wn*64, wn*64+64)
    bool isU = (int)blockIdx.x < blocksU;
    int bidl = isU ? blockIdx.x : (blockIdx.x - blocksU);
    int m0 = bidl * 128;
    int M  = isU ? NU : NI;
    int np = isU ? 2 : 3;
    const float* Ap[3];
    int wp[3];
    if (isU) { Ap[0] = g_meanR; Ap[1] = xu; Ap[2] = xu; wp[0] = 0; wp[1] = 1; wp[2] = 1; }
    else     { Ap[0] = g_meanB; Ap[1] = g_meanT; Ap[2] = xi; wp[0] = 2; wp[1] = 3; wp[2] = 4; }
    float* Cout = isU ? out_user : out_item;
    const float* bias = isU ? g_biasU : g_biasI;

    // acc[s][nt2][4]: s = m16 strip (0,1) within warp's m32; nt2 = n8 tile (0..7) within n64
    float acc[2][8][4];
    #pragma unroll
    for (int s = 0; s < 2; s++)
        #pragma unroll
        for (int i = 0; i < 8; i++)
            #pragma unroll
            for (int j = 0; j < 4; j++) acc[s][i][j] = 0.f;

    int a_row = lane & 15;
    int a_kh  = (lane >> 4) << 3;
    int b_n   = (lane & 7) + ((lane >> 4) << 3);
    int b_kh  = ((lane >> 3) & 1) << 3;

    for (int p = 0; p < np; p++) {
        const float* A = Ap[p];
        const __nv_bfloat16* WHsrc = g_Wsp[wp[p]][0];
        const __nv_bfloat16* WLsrc = g_Wsp[wp[p]][1];
        for (int c = 0; c < 2; c++) {
            __syncthreads();   // protect previous iteration's smem reads
            // ---- W chunk via cp.async (overlaps with A convert below)
            #pragma unroll
            for (int it = 0; it < 4; it++) {
                int q = tid + it * 256;
                int n = q >> 3;
                int j = q & 7;
                cpa16(sWh + (n * TSTRIDE + j * 8) * 2, WHsrc + n * 128 + c * 64 + j * 8);
                cpa16(sWl + (n * TSTRIDE + j * 8) * 2, WLsrc + n * 128 + c * 64 + j * 8);
            }
            CPA_COMMIT();
            // ---- load & split A chunk [128 m x 64 k]
            #pragma unroll
            for (int it = 0; it < 8; it++) {
                int q = tid + it * 256;
                int row = q >> 4;
                int k4  = (q & 15) << 2;
                int grow = m0 + row;
                float4 v = make_float4(0.f, 0.f, 0.f, 0.f);
                if (grow < M) v = *(const float4*)(A + (size_t)grow * DIMN + c * 64 + k4);
                __nv_bfloat16 h0 = __float2bfloat16_rn(v.x);
                __nv_bfloat16 h1 = __float2bfloat16_rn(v.y);
                __nv_bfloat16 h2 = __float2bfloat16_rn(v.z);
                __nv_bfloat16 h3 = __float2bfloat16_rn(v.w);
                ushort4 uh = make_ushort4(__bfloat16_as_ushort(h0), __bfloat16_as_ushort(h1),
                                          __bfloat16_as_ushort(h2), __bfloat16_as_ushort(h3));
                __nv_bfloat16 l0 = __float2bfloat16_rn(v.x - __bfloat162float(h0));
                __nv_bfloat16 l1 = __float2bfloat16_rn(v.y - __bfloat162float(h1));
                __nv_bfloat16 l2 = __float2bfloat16_rn(v.z - __bfloat162float(h2));
                __nv_bfloat16 l3 = __float2bfloat16_rn(v.w - __bfloat162float(h3));
                ushort4 ul = make_ushort4(__bfloat16_as_ushort(l0), __bfloat16_as_ushort(l1),
                                          __bfloat16_as_ushort(l2), __bfloat16_as_ushort(l3));
                *(ushort4*)(Ah + row * TSTRIDE + k4) = uh;
                *(ushort4*)(Al + row * TSTRIDE + k4) = ul;
            }
            CPA_WAIT0();
            __syncthreads();
            // ---- compute: warp (wm, wn) owns m32 x n64
            #pragma unroll
            for (int ks = 0; ks < 4; ks++) {
                uint32_t aH[2][4], aL[2][4];
                #pragma unroll
                for (int s = 0; s < 2; s++) {
                    uint32_t aoff = (uint32_t)((wm * 32 + s * 16 + a_row) * TSTRIDE
                                               + ks * 16 + a_kh) * 2;
                    ldsm4(aH[s], sAh + aoff);
                    ldsm4(aL[s], sAl + aoff);
                }
                #pragma unroll
                for (int nt = 0; nt < 4; nt++) {
                    uint32_t bH[4], bL[4];
                    uint32_t boff = (uint32_t)((wn * 64 + nt * 16 + b_n) * TSTRIDE
                                               + ks * 16 + b_kh) * 2;
                    ldsm4(bH, sWh + boff);
                    ldsm4(bL, sWl + boff);
                    #pragma unroll
                    for (int s = 0; s < 2; s++) {
                        mma16816(acc[s][nt * 2],     aH[s], bH[0], bH[1]);
                        mma16816(acc[s][nt * 2 + 1], aH[s], bH[2], bH[3]);
                        mma16816(acc[s][nt * 2],     aH[s], bL[0], bL[1]);
                        mma16816(acc[s][nt * 2 + 1], aH[s], bL[2], bL[3]);
                        mma16816(acc[s][nt * 2],     aL[s], bH[0], bH[1]);
                        mma16816(acc[s][nt * 2 + 1], aL[s], bH[2], bH[3]);
                    }
                }
            }
        }
    }

    // ---- epilogue
    int ncol = (lane & 3) * 2;
    #pragma unroll
    for (int s = 0; s < 2; s++) {
        int row0 = m0 + wm * 32 + s * 16 + (lane >> 2);
        int row1 = row0 + 8;
        #pragma unroll
        for (int t8 = 0; t8 < 8; t8++) {
            int n = wn * 64 + t8 * 8 + ncol;
            float2 bv = *(const float2*)(bias + n);
            if (row0 < M) {
                float2 o = make_float2(acc[s][t8][0] + bv.x, acc[s][t8][1] + bv.y);
                *(float2*)(Cout + (size_t)row0 * DIMN + n) = o;
            }
            if (row1 < M) {
                float2 o = make_float2(acc[s][t8][2] + bv.x, acc[s][t8][3] + bv.y);
                *(float2*)(Cout + (size_t)row1 * DIMN + n) = o;
            }
        }
    }
}

// ---------------- launch ----------------
extern "C" void kernel_launch(void* const* d_in, const int* in_sizes, int n_in,
                              void* d_out, int out_size) {
    const float* xu  = (const float*)d_in[0];
    const float* xi  = (const float*)d_in[1];
    const float* xt  = (const float*)d_in[2];
    const int*   eb  = (const int*)d_in[3];
    const int*   er  = (const int*)d_in[4];
    const int*   et  = (const int*)d_in[5];
    const float* WlB = (const float*)d_in[6];
    const float* WrB = (const float*)d_in[7];
    const float* bB  = (const float*)d_in[8];
    const float* WlR = (const float*)d_in[9];
    const float* WrR = (const float*)d_in[10];
    const float* bR  = (const float*)d_in[11];
    const float* WlT = (const float*)d_in[12];
    const float* WrT = (const float*)d_in[13];
    const float* bT  = (const float*)d_in[14];

    int NU = in_sizes[0] / DIMN;
    int NI = in_sizes[1] / DIMN;
    int EB = in_sizes[3] / 2;
    int ER = in_sizes[4] / 2;
    int ET = in_sizes[5] / 2;

    float* out_user = (float*)d_out;
    float* out_item = (float*)d_out + (size_t)NU * DIMN;

    int Etot = EB + ER + ET;

    k_init<<<(3 * (NU_MAX + 1) + 255) / 256, 256>>>(WlR, WrR, WlB, WlT, WrB, WrT,
                                                    bR, bB, bT);
    k_hist3<<<(Etot / 2 + 256) / 256, 256>>>(eb + EB, er + ER, et + ET, EB, ER, ET);
    k_scan<<<3, 1024>>>(NI, NU, NI);
    k_fill3<<<(Etot / 2 + 256) / 256, 256>>>(eb, er, et, EB, ER, ET);

    int totalNodes = NI + NU + NI;
    k_agg3<<<(totalNodes * 32 + 255) / 256, 256>>>(xu, xi, xt, NU, NI);

    const int SMEM_BYTES = 4 * 128 * TSTRIDE * 2;   // 73728
    cudaFuncSetAttribute(k_gemm_mma, cudaFuncAttributeMaxDynamicSharedMemorySize, SMEM_BYTES);
    int blocksU = (NU + 127) / 128;
    int blocksI = (NI + 127) / 128;
    k_gemm_mma<<<blocksU + blocksI, 256, SMEM_BYTES>>>(xu, xi, out_user, out_item,
                                                       NU, NI, blocksU);
}